// round 7
// baseline (speedup 1.0000x reference)
#include <cuda_runtime.h>

// Geometry: thread owns 4 rows x 2 cols (one u64). Warp = 32 u64 = 64 cols.
#define HH    512
#define W2    256            // u64 per row
#define FR2   (HH * W2)      // u64 per channel-frame
#define FS2   (2 * FR2)      // u64 per timestep
#define TC    9              // t-chunks
#define TPC   22             // 198 / 9
#define GX    8              // 256 u64-cols / 32 lanes
#define GY    16             // 512 rows / (8 warps * 4 rows)
#define NBLK  (GX * GY * TC) // 1152

#define DENOM 52107462.0     // 198 * 513 * 513
#define SCALE 6400.0         // (1/DT)^2 deferred from the residual

typedef unsigned long long u64;

__device__ float g_part[NBLK * 2];
__device__ unsigned int g_count = 0;

// ---------- packed f32x2 helpers ----------
__device__ __forceinline__ u64 pk(float a, float b) {
    u64 r; asm("mov.b64 %0, {%1, %2};" : "=l"(r) : "f"(a), "f"(b)); return r;
}
__device__ __forceinline__ void upk(u64 v, float& a, float& b) {
    asm("mov.b64 {%0, %1}, %2;" : "=f"(a), "=f"(b) : "l"(v));
}
__device__ __forceinline__ u64 fadd2(u64 a, u64 b) {
    u64 d; asm("add.rn.f32x2 %0, %1, %2;" : "=l"(d) : "l"(a), "l"(b)); return d;
}
__device__ __forceinline__ u64 fsub2(u64 a, u64 b) {
    u64 d; asm("sub.rn.f32x2 %0, %1, %2;" : "=l"(d) : "l"(a), "l"(b)); return d;
}
__device__ __forceinline__ u64 fmul2(u64 a, u64 b) {
    u64 d; asm("mul.rn.f32x2 %0, %1, %2;" : "=l"(d) : "l"(a), "l"(b)); return d;
}
__device__ __forceinline__ u64 ffma2(u64 a, u64 b, u64 c) {
    u64 d; asm("fma.rn.f32x2 %0, %1, %2, %3;" : "=l"(d) : "l"(a), "l"(b), "l"(c)); return d;
}

// Residual pair for one row, both channels.
__device__ __forceinline__ void row_residual(
    u64 cu, u64 cv, u64 Lu, u64 Ru, u64 Lv, u64 Rv,
    u64 um1, u64 up1, u64 um2, u64 up2,
    u64 vm1, u64 vp1, u64 vm2, u64 vp2,
    u64 nu, u64 nv,
    u64 CC, u64 CN, u64 CF, u64 MDT,
    u64& ru, u64& rv)
{
    float l0, l1, c0, c1, q0, q1;

    upk(Lu, l0, l1); upk(cu, c0, c1); upk(Ru, q0, q1);
    const u64 nearU = fadd2(fadd2(pk(l1, c0), pk(c1, q0)), fadd2(um1, up1));
    const u64 farU  = fadd2(fadd2(Lu, Ru), fadd2(um2, up2));
    const u64 lapU  = ffma2(CN, nearU, ffma2(CF, farU, fmul2(CC, cu)));

    upk(Lv, l0, l1); upk(cv, c0, c1); upk(Rv, q0, q1);
    const u64 nearV = fadd2(fadd2(pk(l1, c0), pk(c1, q0)), fadd2(vm1, vp1));
    const u64 farV  = fadd2(fadd2(Lv, Rv), fadd2(vm2, vp2));
    const u64 lapV  = ffma2(CN, nearV, ffma2(CF, farV, fmul2(CC, cv)));

    const u64 s  = ffma2(cu, cu, fmul2(cv, cv));
    const u64 du = fsub2(nu, cu);
    const u64 dv = fsub2(nv, cv);
    // X_u = u + lap_u + s*(v-u);  X_v = v + lap_v - s*(v+u)
    const u64 Xu = fadd2(cu, ffma2(s, fsub2(cv, cu), lapU));
    const u64 Xv = fadd2(cv, fsub2(lapV, fmul2(s, fadd2(cv, cu))));
    ru = ffma2(Xu, MDT, du);   // du - DT*Xu
    rv = ffma2(Xv, MDT, dv);
}

__global__ __launch_bounds__(256, 3)
void pde_kernel(const float* __restrict__ inF, float* __restrict__ out)
{
    const int tx = threadIdx.x;               // lane
    const int ty = threadIdx.y;               // warp
    const int cp = blockIdx.x * 32 + tx;      // u64 column 0..255
    const int i0 = blockIdx.y * 32 + ty * 4;  // first of 4 rows
    const int t0 = blockIdx.z * TPC;

    const u64* __restrict__ base = (const u64*)inF;

    const u64* pC  = base + (size_t)t0 * FS2 + i0 * W2 + cp;                  // center
    const u64* pm2 = base + (size_t)t0 * FS2 + ((i0 - 2) & 511) * W2 + cp;    // row i0-2
    const u64* pm1 = base + (size_t)t0 * FS2 + ((i0 - 1) & 511) * W2 + cp;    // row i0-1
    const u64* pp4 = base + (size_t)t0 * FS2 + ((i0 + 4) & 511) * W2 + cp;    // row i0+4
    const u64* pp5 = base + (size_t)t0 * FS2 + ((i0 + 5) & 511) * W2 + cp;    // row i0+5
    const u64* pL  = base + (size_t)t0 * FS2 + i0 * W2 + ((cp - 1) & 255);    // left u64
    const u64* pR  = base + (size_t)t0 * FS2 + i0 * W2 + ((cp + 1) & 255);    // right u64

    // constants (MU and DX^2 folded into stencil; 1/DT deferred)
    const float ccf = 0.1f * (-5.0f) * 25.0f;
    const float cnf = 0.1f * (4.0f / 3.0f) * 25.0f;
    const float cff = 0.1f * (-1.0f / 12.0f) * 25.0f;
    const u64 CC  = pk(ccf, ccf);
    const u64 CN  = pk(cnf, cnf);
    const u64 CF  = pk(cff, cff);
    const u64 MDT = pk(-0.0125f, -0.0125f);

    const bool rowdup = (i0 == 0);
    const bool coldup = (cp == 0);

    // carried centers at time t: 4 rows x 2 channels
    u64 cu0 = pC[0 * W2];
    u64 cu1 = pC[1 * W2];
    u64 cu2 = pC[2 * W2];
    u64 cu3 = pC[3 * W2];
    u64 cv0 = pC[FR2 + 0 * W2];
    u64 cv1 = pC[FR2 + 1 * W2];
    u64 cv2 = pC[FR2 + 2 * W2];
    u64 cv3 = pC[FR2 + 3 * W2];

    u64 aU = 0, aV = 0;

    #pragma unroll 1
    for (int it = 0; it < TPC; ++it) {
        u64 ru, rv;

        // ===== Phase A: rows 0,1 =====
        const u64 hm2u = pm2[0];
        const u64 hm2v = pm2[FR2];
        const u64 hm1u = pm1[0];
        const u64 hm1v = pm1[FR2];
        const u64 nu0  = pC[FS2];
        const u64 nv0  = pC[FS2 + FR2];
        const u64 nu1  = pC[FS2 + W2];
        const u64 nv1  = pC[FS2 + FR2 + W2];
        const u64 Lu0  = pL[0];
        const u64 Lv0  = pL[FR2];
        const u64 Lu1  = pL[W2];
        const u64 Lv1  = pL[FR2 + W2];
        const u64 Ru0  = pR[0];
        const u64 Rv0  = pR[FR2];
        const u64 Ru1  = pR[W2];
        const u64 Rv1  = pR[FR2 + W2];

        // row 0: vertical m1=hm1, p1=cu1, m2=hm2, p2=cu2
        row_residual(cu0, cv0, Lu0, Ru0, Lv0, Rv0,
                     hm1u, cu1, hm2u, cu2, hm1v, cv1, hm2v, cv2,
                     nu0, nv0, CC, CN, CF, MDT, ru, rv);
        aU = ffma2(ru, ru, aU);
        aV = ffma2(rv, rv, aV);
        if (rowdup) {                       // duplicated grid row 0
            aU = ffma2(ru, ru, aU);
            aV = ffma2(rv, rv, aV);
        }
        if (coldup) {                       // duplicated grid col 0 (px0 of this u64)
            float a, b;
            upk(ru, a, b); const u64 e1 = pk(a, 0.0f);
            upk(rv, a, b); const u64 e2 = pk(a, 0.0f);
            aU = ffma2(e1, e1, aU);
            aV = ffma2(e2, e2, aV);
            if (rowdup) {                   // corner (0,0): weight 4
                aU = ffma2(e1, e1, aU);
                aV = ffma2(e2, e2, aV);
            }
        }

        // row 1: m1=cu0, p1=cu2, m2=hm1, p2=cu3
        row_residual(cu1, cv1, Lu1, Ru1, Lv1, Rv1,
                     cu0, cu2, hm1u, cu3, cv0, cv2, hm1v, cv3,
                     nu1, nv1, CC, CN, CF, MDT, ru, rv);
        aU = ffma2(ru, ru, aU);
        aV = ffma2(rv, rv, aV);
        if (coldup) {
            float a, b;
            upk(ru, a, b); const u64 e1 = pk(a, 0.0f);
            upk(rv, a, b); const u64 e2 = pk(a, 0.0f);
            aU = ffma2(e1, e1, aU);
            aV = ffma2(e2, e2, aV);
        }

        // ===== Phase B: rows 2,3 =====
        const u64 hp4u = pp4[0];
        const u64 hp4v = pp4[FR2];
        const u64 hp5u = pp5[0];
        const u64 hp5v = pp5[FR2];
        const u64 nu2  = pC[FS2 + 2 * W2];
        const u64 nv2  = pC[FS2 + FR2 + 2 * W2];
        const u64 nu3  = pC[FS2 + 3 * W2];
        const u64 nv3  = pC[FS2 + FR2 + 3 * W2];
        const u64 Lu2  = pL[2 * W2];
        const u64 Lv2  = pL[FR2 + 2 * W2];
        const u64 Lu3  = pL[3 * W2];
        const u64 Lv3  = pL[FR2 + 3 * W2];
        const u64 Ru2  = pR[2 * W2];
        const u64 Rv2  = pR[FR2 + 2 * W2];
        const u64 Ru3  = pR[3 * W2];
        const u64 Rv3  = pR[FR2 + 3 * W2];

        // row 2: m1=cu1, p1=cu3, m2=cu0, p2=hp4
        row_residual(cu2, cv2, Lu2, Ru2, Lv2, Rv2,
                     cu1, cu3, cu0, hp4u, cv1, cv3, cv0, hp4v,
                     nu2, nv2, CC, CN, CF, MDT, ru, rv);
        aU = ffma2(ru, ru, aU);
        aV = ffma2(rv, rv, aV);
        if (coldup) {
            float a, b;
            upk(ru, a, b); const u64 e1 = pk(a, 0.0f);
            upk(rv, a, b); const u64 e2 = pk(a, 0.0f);
            aU = ffma2(e1, e1, aU);
            aV = ffma2(e2, e2, aV);
        }

        // row 3: m1=cu2, p1=hp4, m2=cu1, p2=hp5
        row_residual(cu3, cv3, Lu3, Ru3, Lv3, Rv3,
                     cu2, hp4u, cu1, hp5u, cv2, hp4v, cv1, hp5v,
                     nu3, nv3, CC, CN, CF, MDT, ru, rv);
        aU = ffma2(ru, ru, aU);
        aV = ffma2(rv, rv, aV);
        if (coldup) {
            float a, b;
            upk(ru, a, b); const u64 e1 = pk(a, 0.0f);
            upk(rv, a, b); const u64 e2 = pk(a, 0.0f);
            aU = ffma2(e1, e1, aU);
            aV = ffma2(e2, e2, aV);
        }

        // slide in time
        cu0 = nu0; cu1 = nu1; cu2 = nu2; cu3 = nu3;
        cv0 = nv0; cv1 = nv1; cv2 = nv2; cv3 = nv3;
        pC += FS2; pm2 += FS2; pm1 += FS2; pp4 += FS2; pp5 += FS2;
        pL += FS2; pR += FS2;
    }

    // fold packed accumulators
    float a, b;
    upk(aU, a, b); float sum_u = a + b;
    upk(aV, a, b); float sum_v = a + b;

    #pragma unroll
    for (int off = 16; off > 0; off >>= 1) {
        sum_u += __shfl_down_sync(0xffffffffu, sum_u, off);
        sum_v += __shfl_down_sync(0xffffffffu, sum_v, off);
    }

    __shared__ float su[8], sv[8];
    __shared__ bool isLast;
    if (tx == 0) { su[ty] = sum_u; sv[ty] = sum_v; }
    __syncthreads();

    const int tid = ty * 32 + tx;
    if (tid == 0) {
        float pa = 0.0f, pb = 0.0f;
        #pragma unroll
        for (int k = 0; k < 8; ++k) { pa += su[k]; pb += sv[k]; }
        const int blk = (blockIdx.z * GY + blockIdx.y) * GX + blockIdx.x;
        g_part[blk * 2 + 0] = pa;
        g_part[blk * 2 + 1] = pb;
        __threadfence();
        const unsigned int old = atomicAdd(&g_count, 1);
        isLast = (old == (unsigned int)(NBLK - 1));
    }
    __syncthreads();

    if (isLast) {
        __threadfence();
        double da = 0.0, db = 0.0;
        for (int k = tid; k < NBLK; k += 256) {
            da += (double)g_part[2 * k + 0];
            db += (double)g_part[2 * k + 1];
        }
        __shared__ double sa[256], sb[256];
        sa[tid] = da; sb[tid] = db;
        __syncthreads();
        #pragma unroll
        for (int s = 128; s > 0; s >>= 1) {
            if (tid < s) { sa[tid] += sa[tid + s]; sb[tid] += sb[tid + s]; }
            __syncthreads();
        }
        if (tid == 0) {
            out[0] = (float)(sa[0] * SCALE / DENOM);
            out[1] = (float)(sb[0] * SCALE / DENOM);
            g_count = 0;
        }
    }
}

extern "C" void kernel_launch(void* const* d_in, const int* in_sizes, int n_in,
                              void* d_out, int out_size) {
    (void)in_sizes; (void)n_in; (void)out_size;
    const float* in = (const float*)d_in[0];
    float* out = (float*)d_out;

    dim3 grid(GX, GY, TC);
    dim3 block(32, 8);
    pde_kernel<<<grid, block>>>(in, out);
}